// round 8
// baseline (speedup 1.0000x reference)
#include <cuda_runtime.h>
#include <cuda_fp16.h>
#include <cstdint>

#define T_DIM 1024
#define BT 128
#define BS 64
#define KSF 68           // K f32 smem row stride (words): lane banks 8*m4+g distinct
#define VSF 72           // V f32 smem row stride (words): lane banks 8*g+2*m4 distinct
#define BUF_WORDS (64 * KSF + 64 * VSF)   // 8960 floats per buffer

// bit-packed mask: 8 batches x 1024 rows x 1024 bits = 1 MB
__device__ __align__(16) uint32_t g_maskbits[8u * 1024u * 32u];

__device__ __forceinline__ float ex2(float x) {
    float r; asm("ex2.approx.f32 %0, %1;" : "=f"(r) : "f"(x)); return r;
}
__device__ __forceinline__ uint32_t packh2(float lo, float hi) {
    __half2 h = __floats2half2_rn(lo, hi);   // .x = lo (low 16 bits)
    return *(uint32_t*)&h;
}
__device__ __forceinline__ void cp16(uint32_t dst, const float* src) {
    asm volatile("cp.async.cg.shared.global [%0], [%1], 16;" :: "r"(dst), "l"(src));
}

__device__ __forceinline__ void mma_f16(float d[4], const uint32_t a[4],
                                        uint32_t b0, uint32_t b1) {
    asm volatile(
        "mma.sync.aligned.m16n8k16.row.col.f32.f16.f16.f32 "
        "{%0,%1,%2,%3}, {%4,%5,%6,%7}, {%8,%9}, {%0,%1,%2,%3};\n"
        : "+f"(d[0]), "+f"(d[1]), "+f"(d[2]), "+f"(d[3])
        : "r"(a[0]), "r"(a[1]), "r"(a[2]), "r"(a[3]), "r"(b0), "r"(b1));
}

// ---------------- mask pre-pack (int32 -> bits) ----------------
__global__ void pack_mask_bits_kernel(const int* __restrict__ m) {
    uint32_t w = blockIdx.x * 256 + threadIdx.x;
    const int4* p = (const int4*)(m + (size_t)w * 32);
    uint32_t bits = 0;
    #pragma unroll
    for (int j = 0; j < 8; j++) {
        int4 v = p[j];
        bits |= (v.x != 0 ? 1u : 0u) << (4 * j + 0);
        bits |= (v.y != 0 ? 1u : 0u) << (4 * j + 1);
        bits |= (v.z != 0 ? 1u : 0u) << (4 * j + 2);
        bits |= (v.w != 0 ? 1u : 0u) << (4 * j + 3);
    }
    g_maskbits[w] = bits;
}

__global__ __launch_bounds__(128, 3) void attn_flash_kernel(
    const float* __restrict__ qkv,
    const float* __restrict__ qk_bias,
    float* __restrict__ out)
{
    extern __shared__ __align__(16) float dyns[];

    const int tile_t = blockIdx.x;   // 0..7
    const int bh = blockIdx.y;       // 0..127
    const int tid = threadIdx.x;
    const int wid = tid >> 5;        // 4 warps
    const int lane = tid & 31;
    const int g = lane >> 2;
    const int m4 = lane & 3;

    const float* qp = qkv + (size_t)bh * 192 * T_DIM;
    const float* kp = qp + 64 * T_DIM;
    const float* vp = qp + 128 * T_DIM;
    const uint32_t* mb = g_maskbits + (size_t)(bh & 7) * 1024u * 32u;

    const int t0c = tile_t * BT;
    const int tb = wid * 32;
    const int t0 = t0c + tb;
    const float bias2 = qk_bias[0] * 1.4426950408889634f;
    const float scale2 = 0.125f * 1.4426950408889634f;

    // mask row bases (fixed across stages)
    const uint32_t* mrow0l = mb + (size_t)(t0 + g) * 32;
    const uint32_t* mrow0h = mb + (size_t)(t0 + g + 8) * 32;
    const uint32_t* mrow1l = mb + (size_t)(t0 + 16 + g) * 32;
    const uint32_t* mrow1h = mb + (size_t)(t0 + 24 + g) * 32;

    // ---- Q fragments (fp16 m16n8k16 A layout), loaded once ----
    uint32_t qf[2][4][4];
    #pragma unroll
    for (int r = 0; r < 2; r++) {
        const int t = t0 + 16 * r + g;
        #pragma unroll
        for (int k4 = 0; k4 < 4; k4++) {
            const int c0 = 16 * k4 + 2 * m4;
            qf[r][k4][0] = packh2(qp[(size_t)c0 * T_DIM + t],           qp[(size_t)(c0 + 1) * T_DIM + t]);
            qf[r][k4][1] = packh2(qp[(size_t)c0 * T_DIM + t + 8],       qp[(size_t)(c0 + 1) * T_DIM + t + 8]);
            qf[r][k4][2] = packh2(qp[(size_t)(c0 + 8) * T_DIM + t],     qp[(size_t)(c0 + 9) * T_DIM + t]);
            qf[r][k4][3] = packh2(qp[(size_t)(c0 + 8) * T_DIM + t + 8], qp[(size_t)(c0 + 9) * T_DIM + t + 8]);
        }
    }

    float o[2][8][4];
    #pragma unroll
    for (int r = 0; r < 2; r++)
        #pragma unroll
        for (int n = 0; n < 8; n++)
            { o[r][n][0]=0.f; o[r][n][1]=0.f; o[r][n][2]=0.f; o[r][n][3]=0.f; }
    float lr[2]  = {0.f, 0.f};
    float lrh[2] = {0.f, 0.f};

    const uint32_t smem_base = (uint32_t)__cvta_generic_to_shared(dyns);
    const int crow = tid >> 4;          // staging row base
    const int cj = tid & 15;            // 16B chunk in row

    // ---- prologue: issue stage 0 loads into buffer 0 ----
    {
        const uint32_t kb = smem_base;
        const uint32_t vb = smem_base + 64 * KSF * 4;
        #pragma unroll
        for (int it = 0; it < 8; it++) {
            int c = crow + it * 8;
            cp16(kb + (uint32_t)(c * KSF + cj * 4) * 4, kp + (size_t)c * T_DIM + cj * 4);
            cp16(vb + (uint32_t)(c * VSF + cj * 4) * 4, vp + (size_t)c * T_DIM + cj * 4);
        }
        asm volatile("cp.async.commit_group;" ::: "memory");
    }

    for (int st = 0; st < 16; st++) {
        asm volatile("cp.async.wait_group 0;" ::: "memory");
        __syncthreads();

        // ---- issue next stage's loads into the other buffer ----
        if (st < 15) {
            const int s1 = (st + 1) * BS;
            const uint32_t base1 = smem_base + (uint32_t)(((st + 1) & 1) * BUF_WORDS) * 4;
            const uint32_t kb = base1;
            const uint32_t vb = base1 + 64 * KSF * 4;
            #pragma unroll
            for (int it = 0; it < 8; it++) {
                int c = crow + it * 8;
                cp16(kb + (uint32_t)(c * KSF + cj * 4) * 4, kp + (size_t)c * T_DIM + s1 + cj * 4);
                cp16(vb + (uint32_t)(c * VSF + cj * 4) * 4, vp + (size_t)c * T_DIM + s1 + cj * 4);
            }
            asm volatile("cp.async.commit_group;" ::: "memory");
        }

        const float* Kc = dyns + (st & 1) * BUF_WORDS;
        const float* Vc = Kc + 64 * KSF;

        // ---- hoisted mask bit loads ----
        uint2 m0l = *(const uint2*)(mrow0l + st * 2);
        uint2 m0h = *(const uint2*)(mrow0h + st * 2);
        uint2 m1l = *(const uint2*)(mrow1l + st * 2);
        uint2 m1h = *(const uint2*)(mrow1h + st * 2);

        // ==== process s-halves: S n-blocks [4h, 4h+4) -> softmax -> PV k4 in {2h, 2h+1} ====
        #pragma unroll
        for (int h = 0; h < 2; h++) {
            // ---- S = Q^T K for 4 n-blocks ----
            float sacc[2][4][4];
            #pragma unroll
            for (int r = 0; r < 2; r++)
                #pragma unroll
                for (int n = 0; n < 4; n++)
                    { sacc[r][n][0]=0.f; sacc[r][n][1]=0.f; sacc[r][n][2]=0.f; sacc[r][n][3]=0.f; }
            #pragma unroll
            for (int k4 = 0; k4 < 4; k4++) {
                const float* kr0 = Kc + (16 * k4 + 2 * m4) * KSF;
                const float* kr1 = kr0 + KSF;
                const float* kr2 = kr0 + 8 * KSF;
                const float* kr3 = kr0 + 9 * KSF;
                #pragma unroll
                for (int n = 0; n < 4; n++) {
                    const int s = 8 * (4 * h + n) + g;
                    uint32_t b0 = packh2(kr0[s], kr1[s]);
                    uint32_t b1 = packh2(kr2[s], kr3[s]);
                    mma_f16(sacc[0][n], qf[0][k4], b0, b1);
                    mma_f16(sacc[1][n], qf[1][k4], b0, b1);
                }
            }

            // ---- mask + exp2 + row sums (mask word: h=0 -> .x, h=1 -> .y) ----
            #pragma unroll
            for (int r = 0; r < 2; r++) {
                uint32_t lw = (r == 0) ? (h == 0 ? m0l.x : m0l.y) : (h == 0 ? m1l.x : m1l.y);
                uint32_t hw = (r == 0) ? (h == 0 ? m0h.x : m0h.y) : (h == 0 ? m1h.x : m1h.y);
                uint32_t lx = lw >> (2 * m4);
                uint32_t hx = hw >> (2 * m4);
                #pragma unroll
                for (int n = 0; n < 4; n++) {
                    uint32_t wl = lx >> (8 * n);
                    uint32_t wh = hx >> (8 * n);
                    float e00 = ex2(fmaf(sacc[r][n][0], scale2, bias2));
                    float e01 = ex2(fmaf(sacc[r][n][1], scale2, bias2));
                    float e10 = ex2(fmaf(sacc[r][n][2], scale2, bias2));
                    float e11 = ex2(fmaf(sacc[r][n][3], scale2, bias2));
                    float p00 = (wl & 1u) ? e00 : 0.f;
                    float p01 = (wl & 2u) ? e01 : 0.f;
                    float p10 = (wh & 1u) ? e10 : 0.f;
                    float p11 = (wh & 2u) ? e11 : 0.f;
                    sacc[r][n][0] = p00; sacc[r][n][1] = p01;
                    sacc[r][n][2] = p10; sacc[r][n][3] = p11;
                    lr[r]  += p00 + p01;
                    lrh[r] += p10 + p11;
                }
            }

            // ---- O += P V^T for k4 in {2h, 2h+1} (A-frag = packed S C-frag pairs) ----
            #pragma unroll
            for (int kk = 0; kk < 2; kk++) {
                const int k4 = 2 * h + kk;
                uint32_t a0[4], a1[4];
                a0[0] = packh2(sacc[0][2 * kk][0],     sacc[0][2 * kk][1]);
                a0[1] = packh2(sacc[0][2 * kk][2],     sacc[0][2 * kk][3]);
                a0[2] = packh2(sacc[0][2 * kk + 1][0], sacc[0][2 * kk + 1][1]);
                a0[3] = packh2(sacc[0][2 * kk + 1][2], sacc[0][2 * kk + 1][3]);
                a1[0] = packh2(sacc[1][2 * kk][0],     sacc[1][2 * kk][1]);
                a1[1] = packh2(sacc[1][2 * kk][2],     sacc[1][2 * kk][3]);
                a1[2] = packh2(sacc[1][2 * kk + 1][0], sacc[1][2 * kk + 1][1]);
                a1[3] = packh2(sacc[1][2 * kk + 1][2], sacc[1][2 * kk + 1][3]);
                #pragma unroll
                for (int n = 0; n < 8; n++) {
                    const float* vr = Vc + (8 * n + g) * VSF + 16 * k4 + 2 * m4;
                    float2 v0 = *(const float2*)vr;
                    float2 v1 = *(const float2*)(vr + 8);
                    uint32_t b0 = packh2(v0.x, v0.y);
                    uint32_t b1 = packh2(v1.x, v1.y);
                    mma_f16(o[0][n], a0, b0, b1);
                    mma_f16(o[1][n], a1, b0, b1);
                }
            }
        }
    }

    // ---- deferred row-sum reduction ----
    #pragma unroll
    for (int r = 0; r < 2; r++) {
        lr[r]  += __shfl_xor_sync(0xffffffffu, lr[r], 1);
        lr[r]  += __shfl_xor_sync(0xffffffffu, lr[r], 2);
        lrh[r] += __shfl_xor_sync(0xffffffffu, lrh[r], 1);
        lrh[r] += __shfl_xor_sync(0xffffffffu, lrh[r], 2);
    }

    float* ob = out + (size_t)bh * 64 * T_DIM;
    #pragma unroll
    for (int r = 0; r < 2; r++) {
        float il0 = 1.f / lr[r];
        float il1 = 1.f / lrh[r];
        #pragma unroll
        for (int n = 0; n < 8; n++) {
            int c = 8 * n + 2 * m4;
            int t = t0 + 16 * r + g;
            ob[(size_t)c       * T_DIM + t]     = o[r][n][0] * il0;
            ob[(size_t)(c + 1) * T_DIM + t]     = o[r][n][1] * il0;
            ob[(size_t)c       * T_DIM + t + 8] = o[r][n][2] * il1;
            ob[(size_t)(c + 1) * T_DIM + t + 8] = o[r][n][3] * il1;
        }
    }
}

extern "C" void kernel_launch(void* const* d_in, const int* in_sizes, int n_in,
                              void* d_out, int out_size) {
    const float* qkv = (const float*)d_in[0];
    const int* mask = (const int*)d_in[1];
    const float* bias = (const float*)d_in[2];
    float* out = (float*)d_out;

    pack_mask_bits_kernel<<<1024, 256>>>(mask);

    const int dyn_smem = 2 * BUF_WORDS * 4;   // 71680 B
    static int attr_set = 0;
    if (!attr_set) {
        cudaFuncSetAttribute(attn_flash_kernel,
                             cudaFuncAttributeMaxDynamicSharedMemorySize, dyn_smem);
        attr_set = 1;
    }
    dim3 grid(T_DIM / BT, 8 * 16);
    attn_flash_kernel<<<grid, 128, dyn_smem>>>(qkv, bias, out);
}